// round 13
// baseline (speedup 1.0000x reference)
#include <cuda_runtime.h>
#include <cuda_bf16.h>
#include <math.h>
#include <stdint.h>

// ---------------------------------------------------------------------------
// QuantumHybridCNN, bf16 MMA.
//  k_conv: persistent, double-buffered, pipelined conv1+conv2 (R11 winner) +
//          one-time packing of fcw into g_fcwp [cc][col][kp] layout.
//  k_fc:   fc GEMM M=64 N=64 K=1024, cp.async 3-stage ring + ldmatrix.x4
//          fragment loads (A row-major [row][36], B col-major [col][36]),
//          + pre + tanh + 4-qubit circuit + post + sigmoid.
// h2p[b][q]: q = pos*32 + kp32, u32 = bf16x2(ch, ch+8), ch=(kp>>3)*16+(kp&7).
// g_fcwp[cc][col][kp] = bf16x2(fcw[ch*16+cc][col], fcw[(ch+8)*16+cc][col]).
// ---------------------------------------------------------------------------

#define BMAX 32768
__device__ uint32_t g_h2p[(size_t)BMAX * 512];
__device__ uint32_t g_fcwp[16 * 2048];

__device__ __forceinline__ uint32_t packbf(float lo, float hi) {
    __nv_bfloat162 h = __floats2bfloat162_rn(lo, hi);
    return *(uint32_t*)&h;
}

__device__ __forceinline__ void mma16(float d[4], const uint32_t a[4],
                                      uint32_t b0, uint32_t b1) {
    asm volatile(
        "mma.sync.aligned.m16n8k16.row.col.f32.bf16.bf16.f32 "
        "{%0,%1,%2,%3}, {%4,%5,%6,%7}, {%8,%9}, {%0,%1,%2,%3};"
        : "+f"(d[0]), "+f"(d[1]), "+f"(d[2]), "+f"(d[3])
        : "r"(a[0]), "r"(a[1]), "r"(a[2]), "r"(a[3]), "r"(b0), "r"(b1));
}

__device__ __forceinline__ void ldsm4(uint32_t& r0, uint32_t& r1,
                                      uint32_t& r2, uint32_t& r3,
                                      uint32_t addr) {
    asm volatile("ldmatrix.sync.aligned.m8n8.x4.shared.b16 {%0,%1,%2,%3}, [%4];"
                 : "=r"(r0), "=r"(r1), "=r"(r2), "=r"(r3) : "r"(addr));
}

__device__ __forceinline__ void cpasync16(uint32_t smem_b, const void* g) {
    asm volatile("cp.async.ca.shared.global [%0], [%1], 16;"
                 :: "r"(smem_b), "l"(g));
}
__device__ __forceinline__ void cp_commit() {
    asm volatile("cp.async.commit_group;");
}
__device__ __forceinline__ void cp_wait1() {
    asm volatile("cp.async.wait_group 1;");
}

// conv1 + relu + pool (thread owns channel pair; STS staggered, conflict-free)
__device__ __forceinline__ void conv1_phase(
    const float* __restrict__ xr, uint32_t* __restrict__ hrow,
    int cp, int sub, int mh, int m8,
    float wA0, float wA1, float wA2, float bA,
    float wB0, float wB1, float wB2, float bB)
{
    #pragma unroll
    for (int i = 0; i < 8; i++) {
        int o = (m8 + i) & 7;
        int j = mh * 16 + sub * 8 + o;
        int pp = 2 * j;
        float xm  = (pp == 0)  ? 0.0f : xr[pp - 1];
        float x0  = xr[pp], x1 = xr[pp + 1];
        float xp2 = (pp == 62) ? 0.0f : xr[pp + 2];
        float ya0 = fmaf(wA0, xm, fmaf(wA1, x0, fmaf(wA2, x1,  bA)));
        float ya1 = fmaf(wA0, x0, fmaf(wA1, x1, fmaf(wA2, xp2, bA)));
        float yb0 = fmaf(wB0, xm, fmaf(wB1, x0, fmaf(wB2, x1,  bB)));
        float yb1 = fmaf(wB0, x0, fmaf(wB1, x1, fmaf(wB2, xp2, bB)));
        float vA = fmaxf(fmaxf(ya0, ya1), 0.0f);
        float vB = fmaxf(fmaxf(yb0, yb1), 0.0f);
        hrow[cp * 40 + j + 1] = packbf(vA, vB);
    }
}

// ---------------------------------------------------------------------------
// Kernel 1: conv1 + conv2, persistent + pipelined + fcw packing.
// ---------------------------------------------------------------------------
#define CV_XS 0
#define CV_HP 512
#define CV_WP (CV_HP + 5120)
#define CV_BS (CV_WP + 3456)
#define CV_SMEM_U32 (CV_BS + 64)
#define CONV_GRID 296

__global__ void __launch_bounds__(256, 2) k_conv(
    const float* __restrict__ x,
    const float* __restrict__ c1w, const float* __restrict__ c1b,
    const float* __restrict__ c2w, const float* __restrict__ c2b,
    const float* __restrict__ fcw,
    uint32_t* __restrict__ h2p, uint32_t* __restrict__ fcwp,
    int B, int ntiles)
{
    extern __shared__ float smf[];
    uint32_t* smu = (uint32_t*)smf;
    float*    xs  = smf + CV_XS;      // [2 buf][4 samples][64]
    uint32_t* hp  = smu + CV_HP;      // [2 buf][4 samples][16 cp][40]
    uint32_t* wpT = smu + CV_WP;      // [48 kp][72]
    float*    bs  = smf + CV_BS;      // [64]

    int tid = threadIdx.x;
    int lane = tid & 31, warp = tid >> 5;
    int gid = lane >> 2, tid4 = lane & 3;
    int sl = warp & 3;
    int mh = warp >> 2;

    // ---- one-time: pack fcw -> fcwp[cc][col][kp] (1 u32 / thread) ----
    {
        int i = blockIdx.x * 256 + tid;
        if (i < 32768) {
            int cc = i >> 11, col = (i >> 5) & 63, kp = i & 31;
            int ch = ((kp >> 3) << 4) + (kp & 7);
            fcwp[i] = packbf(fcw[(ch * 16 + cc) * 64 + col],
                             fcw[((ch + 8) * 16 + cc) * 64 + col]);
        }
    }

    // ---- one-time staging ----
    for (int i = tid; i < 3072; i += 256) {
        int kp = i >> 6, ch = i & 63;
        int k = 2 * kp, t = k >> 5, c = k & 31;
        wpT[kp * 72 + ch] = packbf(c2w[ch * 96 + c * 3 + t],
                                   c2w[ch * 96 + (c + 1) * 3 + t]);
    }
    if (tid < 64) bs[tid] = c2b[tid];
    if (tid < 128) {
        int bf = tid >> 6, s = (tid >> 4) & 3, cp = tid & 15;
        hp[bf * 2560 + s * 640 + cp * 40 + 0]  = 0u;
        hp[bf * 2560 + s * 640 + cp * 40 + 33] = 0u;
    }
    __syncthreads();

    // ---- persistent A fragments (weights) + bias registers ----
    uint32_t aReg[2][6][4];
    float biasReg[2][2];
    #pragma unroll
    for (int mt = 0; mt < 2; mt++) {
        int mtg = mh * 2 + mt;
        biasReg[mt][0] = bs[mtg * 16 + gid];
        biasReg[mt][1] = bs[mtg * 16 + gid + 8];
        #pragma unroll
        for (int ks = 0; ks < 6; ks++) {
            int kp0 = ks * 8;
            aReg[mt][ks][0] = wpT[(kp0 + tid4) * 72 + mtg * 16 + gid];
            aReg[mt][ks][1] = wpT[(kp0 + tid4) * 72 + mtg * 16 + gid + 8];
            aReg[mt][ks][2] = wpT[(kp0 + tid4 + 4) * 72 + mtg * 16 + gid];
            aReg[mt][ks][3] = wpT[(kp0 + tid4 + 4) * 72 + mtg * 16 + gid + 8];
        }
    }

    int cp = lane >> 1, sub = lane & 1;
    int m8 = (cp >> 2) + 4 * sub;
    float wA0 = __ldg(&c1w[(2 * cp) * 3 + 0]);
    float wA1 = __ldg(&c1w[(2 * cp) * 3 + 1]);
    float wA2 = __ldg(&c1w[(2 * cp) * 3 + 2]);
    float bA  = __ldg(&c1b[2 * cp]);
    float wB0 = __ldg(&c1w[(2 * cp + 1) * 3 + 0]);
    float wB1 = __ldg(&c1w[(2 * cp + 1) * 3 + 1]);
    float wB2 = __ldg(&c1w[(2 * cp + 1) * 3 + 2]);
    float bB  = __ldg(&c1b[2 * cp + 1]);

    // ---- prologue ----
    int tile0 = blockIdx.x;
    float xR;
    {
        int gi = tile0 * 256 + tid;
        xR = (tile0 < ntiles && gi < B * 64) ? x[gi] : 0.0f;
        xs[tid] = xR;
    }
    __syncthreads();
    conv1_phase(&xs[sl * 64], hp + sl * 640, cp, sub, mh, m8,
                wA0, wA1, wA2, bA, wB0, wB1, wB2, bB);
    {
        int t1 = tile0 + CONV_GRID;
        int gi = t1 * 256 + tid;
        xR = (t1 < ntiles && gi < B * 64) ? x[gi] : 0.0f;
    }

    int buf = 0;
    for (int tile = tile0; tile < ntiles; tile += CONV_GRID) {
        xs[(buf ^ 1) * 256 + tid] = xR;
        __syncthreads();

        float acc[2][4][4];
        #pragma unroll
        for (int mt = 0; mt < 2; mt++)
            #pragma unroll
            for (int nb = 0; nb < 4; nb++) {
                acc[mt][nb][0] = biasReg[mt][0];
                acc[mt][nb][1] = biasReg[mt][0];
                acc[mt][nb][2] = biasReg[mt][1];
                acc[mt][nb][3] = biasReg[mt][1];
            }
        {
            const uint32_t* hrow = hp + buf * 2560 + sl * 640;
            #pragma unroll
            for (int ks = 0; ks < 6; ks++) {
                int t = ks >> 1, cp0 = (ks & 1) * 8;
                uint32_t b0[4], b1[4];
                #pragma unroll
                for (int nb = 0; nb < 4; nb++) {
                    int col = nb * 8 + gid + t;
                    b0[nb] = hrow[(cp0 + tid4) * 40 + col];
                    b1[nb] = hrow[(cp0 + tid4 + 4) * 40 + col];
                }
                #pragma unroll
                for (int mt = 0; mt < 2; mt++)
                    #pragma unroll
                    for (int nb = 0; nb < 4; nb++)
                        mma16(acc[mt][nb], aReg[mt][ks], b0[nb], b1[nb]);
            }
        }

        conv1_phase(&xs[(buf ^ 1) * 256 + sl * 64],
                    hp + (buf ^ 1) * 2560 + sl * 640, cp, sub, mh, m8,
                    wA0, wA1, wA2, bA, wB0, wB1, wB2, bB);

        {
            int b = tile * 4 + sl;
            if (b < B) {
                uint32_t* dst = h2p + (size_t)b * 512;
                #pragma unroll
                for (int mt = 0; mt < 2; mt++) {
                    int mtg = mh * 2 + mt;
                    #pragma unroll
                    for (int nb = 0; nb < 4; nb++) {
                        float plow  = fmaxf(fmaxf(acc[mt][nb][0], acc[mt][nb][1]), 0.0f);
                        float phigh = fmaxf(fmaxf(acc[mt][nb][2], acc[mt][nb][3]), 0.0f);
                        dst[(nb * 4 + tid4) * 32 + mtg * 8 + gid] = packbf(plow, phigh);
                    }
                }
            }
        }

        {
            int t2 = tile + 2 * CONV_GRID;
            int gi = t2 * 256 + tid;
            xR = (t2 < ntiles && gi < B * 64) ? x[gi] : 0.0f;
        }
        buf ^= 1;
    }
}

// ---------------------------------------------------------------------------
// Quantum helpers.
// ---------------------------------------------------------------------------
__device__ __forceinline__ void apply_ry(float st[16], float th, int mask)
{
    float s, c;
    sincosf(th * 0.5f, &s, &c);
    #pragma unroll
    for (int i = 0; i < 16; i++) {
        if (!(i & mask)) {
            int j = i | mask;
            float a = st[i], b = st[j];
            st[i] = c * a - s * b;
            st[j] = s * a + c * b;
        }
    }
}
__device__ __forceinline__ void apply_cnot(float st[16], int cm, int tm)
{
    #pragma unroll
    for (int i = 0; i < 16; i++) {
        if ((i & cm) && !(i & tm)) {
            int j = i | tm;
            float t = st[i]; st[i] = st[j]; st[j] = t;
        }
    }
}

// ---------------------------------------------------------------------------
// Kernel 2: fc GEMM (cp.async ring + ldmatrix) + pre + tanh + circuit.
// Stage (u32): As [64 rows][36] = 2304 | Bs [64 cols][36] = 2304  -> 4608.
// ---------------------------------------------------------------------------
#define FCS_STG 4608
#define FC_OFF_HS (3 * FCS_STG)
#define FC_OFF_PW (FC_OFF_HS + 64 * 65)
#define FC_OFF_FB (FC_OFF_PW + 256)
#define FC_OFF_PB (FC_OFF_FB + 64)
#define FC_OFF_QP (FC_OFF_PB + 4)
#define FC_OFF_PO (FC_OFF_QP + 24)
#define FC_OFF_QS (FC_OFF_PO + 8)
#define FC_SMEM_U32 (FC_OFF_QS + 256)

__global__ void __launch_bounds__(256, 3) k_fc(
    const uint32_t* __restrict__ h2p, const uint32_t* __restrict__ fcwp,
    const float* __restrict__ fcb, const float* __restrict__ prew,
    const float* __restrict__ preb, const float* __restrict__ qp,
    const float* __restrict__ postw, const float* __restrict__ postb,
    float* __restrict__ out, int B)
{
    extern __shared__ float sm[];
    float* Hs      = sm + FC_OFF_HS;
    float* s_prew  = sm + FC_OFF_PW;
    float* s_fcb   = sm + FC_OFF_FB;
    float* s_preb  = sm + FC_OFF_PB;
    float* s_qp    = sm + FC_OFF_QP;
    float* s_po    = sm + FC_OFF_PO;
    float* qs      = sm + FC_OFF_QS;

    int tid = threadIdx.x;
    int lane = tid & 31, warp = tid >> 5;
    int gid = lane >> 2, tid4 = lane & 3;
    int wm = warp & 3, wn = warp >> 2;
    int b0 = blockIdx.x * 64;

    s_prew[tid] = prew[tid];
    if (tid < 64) s_fcb[tid] = fcb[tid];
    if (tid < 4)  s_preb[tid] = preb[tid];
    if (tid < 24) s_qp[tid] = qp[tid];
    if (tid >= 24 && tid < 28) s_po[tid - 24] = postw[tid - 24];
    if (tid == 28) s_po[4] = postb[0];

    float acc[4][4];
    #pragma unroll
    for (int nb = 0; nb < 4; nb++)
        #pragma unroll
        for (int q = 0; q < 4; q++) acc[nb][q] = 0.0f;

    uint32_t sbase = (uint32_t)__cvta_generic_to_shared(sm);

    // ---- cp.async lane maps ----
    // A: quarter q4 = lane>>3, m = lane&7; row = warp*8+m; quads q4, q4+4.
    int q4 = lane >> 3, m7 = lane & 7;
    int a_row = warp * 8 + m7;
    uint32_t aD0 = (uint32_t)(a_row * 36 + 4 * q4) * 4;
    uint32_t aD1 = (uint32_t)(a_row * 36 + 4 * (q4 + 4)) * 4;
    const uint32_t* a_g = h2p + (size_t)(b0 + a_row) * 512;
    // B: col = tid&63, j = tid>>6 (and j+4); src fcwp[cc][col][4j..]
    int b_col = tid & 63, b_j = tid >> 6;
    uint32_t bD0 = (uint32_t)(2304 + b_col * 36 + 4 * b_j) * 4;
    uint32_t bD1 = (uint32_t)(2304 + b_col * 36 + 4 * (b_j + 4)) * 4;
    const uint32_t* b_g = fcwp + b_col * 32;

    #define FC_ISSUE(cc) do {                                              \
        uint32_t sb = sbase + (uint32_t)(((cc) % 3) * FCS_STG) * 4;        \
        cpasync16(sb + aD0, a_g + (cc) * 32 + 4 * q4);                     \
        cpasync16(sb + aD1, a_g + (cc) * 32 + 4 * (q4 + 4));               \
        cpasync16(sb + bD0, b_g + (cc) * 2048 + 4 * b_j);                  \
        cpasync16(sb + bD1, b_g + (cc) * 2048 + 4 * (b_j + 4));            \
    } while (0)

    // ---- ldmatrix lane maps (byte offsets within stage) ----
    // A x4: lanes 0-7 rows wm*16+0..7 @kp0 | 8-15 +8 | 16-23 @kp0+4 | 24-31 +8
    int a_ld_row = wm * 16 + (lane & 7) + ((lane >> 3) & 1) * 8;
    uint32_t aLd = (uint32_t)(a_ld_row * 36 + (lane >> 4) * 4) * 4;
    // B x4 load0: cols wn*32 + (l&7) + (l>>4)*8, koff ((l>>3)&1)*4
    int b_ld_col = wn * 32 + (lane & 7) + (lane >> 4) * 8;
    uint32_t bLd0 = (uint32_t)(2304 + b_ld_col * 36 + ((lane >> 3) & 1) * 4) * 4;
    uint32_t bLd1 = bLd0 + 16u * 36u * 4u;

    FC_ISSUE(0); cp_commit();
    FC_ISSUE(1); cp_commit();

    for (int cc = 0; cc < 16; cc++) {
        cp_wait1();
        __syncthreads();
        if (cc + 2 < 16) FC_ISSUE(cc + 2);
        cp_commit();

        uint32_t sb = sbase + (uint32_t)((cc % 3) * FCS_STG) * 4;
        #pragma unroll
        for (int ks = 0; ks < 4; ks++) {
            uint32_t kofs = (uint32_t)(ks * 8) * 4;
            uint32_t a[4], bA[4], bB[4];
            ldsm4(a[0], a[1], a[2], a[3], sb + aLd + kofs);
            ldsm4(bA[0], bA[1], bA[2], bA[3], sb + bLd0 + kofs);
            ldsm4(bB[0], bB[1], bB[2], bB[3], sb + bLd1 + kofs);
            mma16(acc[0], a, bA[0], bA[1]);
            mma16(acc[1], a, bA[2], bA[3]);
            mma16(acc[2], a, bB[0], bB[1]);
            mma16(acc[3], a, bB[2], bB[3]);
        }
    }

    // ---- bias + relu -> Hs ----
    #pragma unroll
    for (int nb = 0; nb < 4; nb++) {
        int r = wm * 16 + gid;
        int cb = wn * 32 + nb * 8 + 2 * tid4;
        float bb0 = s_fcb[cb], bb1 = s_fcb[cb + 1];
        Hs[r * 65 + cb]           = fmaxf(acc[nb][0] + bb0, 0.0f);
        Hs[r * 65 + cb + 1]       = fmaxf(acc[nb][1] + bb1, 0.0f);
        Hs[(r + 8) * 65 + cb]     = fmaxf(acc[nb][2] + bb0, 0.0f);
        Hs[(r + 8) * 65 + cb + 1] = fmaxf(acc[nb][3] + bb1, 0.0f);
    }
    __syncthreads();

    // ---- pre: 64 -> 4, tanh * pi/2 -> qs ----
    {
        int s = tid >> 2, wq = tid & 3;
        const float* h = &Hs[s * 65];
        float d = s_preb[wq];
        #pragma unroll 8
        for (int j = 0; j < 64; j++) d = fmaf(h[j], s_prew[j * 4 + wq], d);
        qs[tid] = tanhf(d) * 1.5707963267948966f;
    }
    __syncthreads();

    // ---- quantum circuit + post + sigmoid: threads 0..63 ----
    if (tid < 64 && b0 + tid < B) {
        float q0 = qs[tid * 4 + 0], q1 = qs[tid * 4 + 1];
        float q2 = qs[tid * 4 + 2], q3 = qs[tid * 4 + 3];

        float st[16];
        #pragma unroll
        for (int i = 0; i < 16; i++) st[i] = 0.25f;
        apply_ry(st, q0, 8);
        apply_ry(st, q1, 4);
        apply_ry(st, q2, 2);
        apply_ry(st, q3, 1);
        for (int k = 0; k < 6; k++) {
            apply_cnot(st, 8, 4);
            apply_cnot(st, 2, 1);
            apply_cnot(st, 4, 2);
            apply_ry(st, s_qp[4 * k + 0], 8);
            apply_ry(st, s_qp[4 * k + 1], 4);
            apply_ry(st, s_qp[4 * k + 2], 2);
            apply_ry(st, s_qp[4 * k + 3], 1);
        }

        float z0 = 0.f, z1 = 0.f, z2 = 0.f, z3 = 0.f;
        #pragma unroll
        for (int i = 0; i < 16; i++) {
            float pr = st[i] * st[i];
            z0 += (i & 8) ? -pr : pr;
            z1 += (i & 4) ? -pr : pr;
            z2 += (i & 2) ? -pr : pr;
            z3 += (i & 1) ? -pr : pr;
        }

        float t = s_po[4];
        t = fmaf(z0, s_po[0], t);
        t = fmaf(z1, s_po[1], t);
        t = fmaf(z2, s_po[2], t);
        t = fmaf(z3, s_po[3], t);
        out[b0 + tid] = 1.0f / (1.0f + expf(-t));
    }
}

// ---------------------------------------------------------------------------
extern "C" void kernel_launch(void* const* d_in, const int* in_sizes, int n_in,
                              void* d_out, int out_size)
{
    const float* x       = (const float*)d_in[0];
    const float* conv1_w = (const float*)d_in[1];
    const float* conv1_b = (const float*)d_in[2];
    const float* conv2_w = (const float*)d_in[3];
    const float* conv2_b = (const float*)d_in[4];
    const float* fc_w    = (const float*)d_in[5];
    const float* fc_b    = (const float*)d_in[6];
    const float* pre_w   = (const float*)d_in[7];
    const float* pre_b   = (const float*)d_in[8];
    const float* q_par   = (const float*)d_in[9];
    const float* post_w  = (const float*)d_in[10];
    const float* post_b  = (const float*)d_in[11];
    float* out = (float*)d_out;

    int B = in_sizes[0] / 64;
    if (B > BMAX) B = BMAX;
    int ntiles = (B + 3) / 4;

    uint32_t* h2p;
    uint32_t* fcwp;
    cudaGetSymbolAddress((void**)&h2p, g_h2p);
    cudaGetSymbolAddress((void**)&fcwp, g_fcwp);

    size_t conv_sm = CV_SMEM_U32 * 4;
    size_t fc_sm   = FC_SMEM_U32 * 4;
    cudaFuncSetAttribute(k_conv, cudaFuncAttributeMaxDynamicSharedMemorySize,
                         (int)conv_sm);
    cudaFuncSetAttribute(k_fc, cudaFuncAttributeMaxDynamicSharedMemorySize,
                         (int)fc_sm);

    k_conv<<<CONV_GRID, 256, conv_sm>>>(x, conv1_w, conv1_b, conv2_w, conv2_b,
                                        fc_w, h2p, fcwp, B, ntiles);
    k_fc<<<(B + 63) / 64, 256, fc_sm>>>(h2p, fcwp, fc_b, pre_w, pre_b, q_par,
                                        post_w, post_b, out, B);
}

// round 14
// speedup vs baseline: 1.2354x; 1.2354x over previous
#include <cuda_runtime.h>
#include <cuda_bf16.h>
#include <math.h>
#include <stdint.h>

// ---------------------------------------------------------------------------
// QuantumHybridCNN, bf16 MMA.
//  k_conv: persistent, double-buffered, pipelined conv1+conv2 (R11 winner) +
//          one-time packing of fcw into g_fcwp [cc][kp][col] layout.
//  k_fc:   fc GEMM, 128 samples/block, warp tile m32xn32 (2 LDS wavefronts
//          per MMA), cp.async 3-stage ring, Hs overlaps stage smem.
//          + pre + tanh + 4-qubit circuit + post + sigmoid.
// h2p[b][q]: q = pos*32 + kp32, u32 = bf16x2(ch, ch+8), ch=(kp>>3)*16+(kp&7).
// g_fcwp[cc][kp][col] = bf16x2(fcw[ch*16+cc][col], fcw[(ch+8)*16+cc][col]).
// ---------------------------------------------------------------------------

#define BMAX 32768
__device__ uint32_t g_h2p[(size_t)BMAX * 512];
__device__ uint32_t g_fcwp[16 * 2048];

__device__ __forceinline__ uint32_t packbf(float lo, float hi) {
    __nv_bfloat162 h = __floats2bfloat162_rn(lo, hi);
    return *(uint32_t*)&h;
}

__device__ __forceinline__ void mma16(float d[4], const uint32_t a[4],
                                      uint32_t b0, uint32_t b1) {
    asm volatile(
        "mma.sync.aligned.m16n8k16.row.col.f32.bf16.bf16.f32 "
        "{%0,%1,%2,%3}, {%4,%5,%6,%7}, {%8,%9}, {%0,%1,%2,%3};"
        : "+f"(d[0]), "+f"(d[1]), "+f"(d[2]), "+f"(d[3])
        : "r"(a[0]), "r"(a[1]), "r"(a[2]), "r"(a[3]), "r"(b0), "r"(b1));
}

__device__ __forceinline__ void cpasync16(uint32_t smem_b, const void* g) {
    asm volatile("cp.async.ca.shared.global [%0], [%1], 16;"
                 :: "r"(smem_b), "l"(g));
}
__device__ __forceinline__ void cp_commit() {
    asm volatile("cp.async.commit_group;");
}
__device__ __forceinline__ void cp_wait1() {
    asm volatile("cp.async.wait_group 1;");
}
__device__ __forceinline__ void cp_wait0() {
    asm volatile("cp.async.wait_group 0;");
}

// conv1 + relu + pool (thread owns channel pair; STS staggered, conflict-free)
__device__ __forceinline__ void conv1_phase(
    const float* __restrict__ xr, uint32_t* __restrict__ hrow,
    int cp, int sub, int mh, int m8,
    float wA0, float wA1, float wA2, float bA,
    float wB0, float wB1, float wB2, float bB)
{
    #pragma unroll
    for (int i = 0; i < 8; i++) {
        int o = (m8 + i) & 7;
        int j = mh * 16 + sub * 8 + o;
        int pp = 2 * j;
        float xm  = (pp == 0)  ? 0.0f : xr[pp - 1];
        float x0  = xr[pp], x1 = xr[pp + 1];
        float xp2 = (pp == 62) ? 0.0f : xr[pp + 2];
        float ya0 = fmaf(wA0, xm, fmaf(wA1, x0, fmaf(wA2, x1,  bA)));
        float ya1 = fmaf(wA0, x0, fmaf(wA1, x1, fmaf(wA2, xp2, bA)));
        float yb0 = fmaf(wB0, xm, fmaf(wB1, x0, fmaf(wB2, x1,  bB)));
        float yb1 = fmaf(wB0, x0, fmaf(wB1, x1, fmaf(wB2, xp2, bB)));
        float vA = fmaxf(fmaxf(ya0, ya1), 0.0f);
        float vB = fmaxf(fmaxf(yb0, yb1), 0.0f);
        hrow[cp * 40 + j + 1] = packbf(vA, vB);
    }
}

// ---------------------------------------------------------------------------
// Kernel 1: conv1 + conv2, persistent + pipelined + fcw packing.
// ---------------------------------------------------------------------------
#define CV_XS 0
#define CV_HP 512
#define CV_WP (CV_HP + 5120)
#define CV_BS (CV_WP + 3456)
#define CV_SMEM_U32 (CV_BS + 64)
#define CONV_GRID 296

__global__ void __launch_bounds__(256, 2) k_conv(
    const float* __restrict__ x,
    const float* __restrict__ c1w, const float* __restrict__ c1b,
    const float* __restrict__ c2w, const float* __restrict__ c2b,
    const float* __restrict__ fcw,
    uint32_t* __restrict__ h2p, uint32_t* __restrict__ fcwp,
    int B, int ntiles)
{
    extern __shared__ float smf[];
    uint32_t* smu = (uint32_t*)smf;
    float*    xs  = smf + CV_XS;      // [2 buf][4 samples][64]
    uint32_t* hp  = smu + CV_HP;      // [2 buf][4 samples][16 cp][40]
    uint32_t* wpT = smu + CV_WP;      // [48 kp][72]
    float*    bs  = smf + CV_BS;      // [64]

    int tid = threadIdx.x;
    int lane = tid & 31, warp = tid >> 5;
    int gid = lane >> 2, tid4 = lane & 3;
    int sl = warp & 3;
    int mh = warp >> 2;

    // ---- one-time: pack fcw -> fcwp[cc][kp][col] (1 u32 / thread) ----
    {
        int i = blockIdx.x * 256 + tid;
        if (i < 32768) {
            int cc = i >> 11, kp = (i >> 6) & 31, col = i & 63;
            int ch = ((kp >> 3) << 4) + (kp & 7);
            fcwp[i] = packbf(fcw[(ch * 16 + cc) * 64 + col],
                             fcw[((ch + 8) * 16 + cc) * 64 + col]);
        }
    }

    // ---- one-time staging ----
    for (int i = tid; i < 3072; i += 256) {
        int kp = i >> 6, ch = i & 63;
        int k = 2 * kp, t = k >> 5, c = k & 31;
        wpT[kp * 72 + ch] = packbf(c2w[ch * 96 + c * 3 + t],
                                   c2w[ch * 96 + (c + 1) * 3 + t]);
    }
    if (tid < 64) bs[tid] = c2b[tid];
    if (tid < 128) {
        int bf = tid >> 6, s = (tid >> 4) & 3, cp = tid & 15;
        hp[bf * 2560 + s * 640 + cp * 40 + 0]  = 0u;
        hp[bf * 2560 + s * 640 + cp * 40 + 33] = 0u;
    }
    __syncthreads();

    // ---- persistent A fragments (weights) + bias registers ----
    uint32_t aReg[2][6][4];
    float biasReg[2][2];
    #pragma unroll
    for (int mt = 0; mt < 2; mt++) {
        int mtg = mh * 2 + mt;
        biasReg[mt][0] = bs[mtg * 16 + gid];
        biasReg[mt][1] = bs[mtg * 16 + gid + 8];
        #pragma unroll
        for (int ks = 0; ks < 6; ks++) {
            int kp0 = ks * 8;
            aReg[mt][ks][0] = wpT[(kp0 + tid4) * 72 + mtg * 16 + gid];
            aReg[mt][ks][1] = wpT[(kp0 + tid4) * 72 + mtg * 16 + gid + 8];
            aReg[mt][ks][2] = wpT[(kp0 + tid4 + 4) * 72 + mtg * 16 + gid];
            aReg[mt][ks][3] = wpT[(kp0 + tid4 + 4) * 72 + mtg * 16 + gid + 8];
        }
    }

    int cp = lane >> 1, sub = lane & 1;
    int m8 = (cp >> 2) + 4 * sub;
    float wA0 = __ldg(&c1w[(2 * cp) * 3 + 0]);
    float wA1 = __ldg(&c1w[(2 * cp) * 3 + 1]);
    float wA2 = __ldg(&c1w[(2 * cp) * 3 + 2]);
    float bA  = __ldg(&c1b[2 * cp]);
    float wB0 = __ldg(&c1w[(2 * cp + 1) * 3 + 0]);
    float wB1 = __ldg(&c1w[(2 * cp + 1) * 3 + 1]);
    float wB2 = __ldg(&c1w[(2 * cp + 1) * 3 + 2]);
    float bB  = __ldg(&c1b[2 * cp + 1]);

    // ---- prologue ----
    int tile0 = blockIdx.x;
    float xR;
    {
        int gi = tile0 * 256 + tid;
        xR = (tile0 < ntiles && gi < B * 64) ? x[gi] : 0.0f;
        xs[tid] = xR;
    }
    __syncthreads();
    conv1_phase(&xs[sl * 64], hp + sl * 640, cp, sub, mh, m8,
                wA0, wA1, wA2, bA, wB0, wB1, wB2, bB);
    {
        int t1 = tile0 + CONV_GRID;
        int gi = t1 * 256 + tid;
        xR = (t1 < ntiles && gi < B * 64) ? x[gi] : 0.0f;
    }

    int buf = 0;
    for (int tile = tile0; tile < ntiles; tile += CONV_GRID) {
        xs[(buf ^ 1) * 256 + tid] = xR;
        __syncthreads();

        float acc[2][4][4];
        #pragma unroll
        for (int mt = 0; mt < 2; mt++)
            #pragma unroll
            for (int nb = 0; nb < 4; nb++) {
                acc[mt][nb][0] = biasReg[mt][0];
                acc[mt][nb][1] = biasReg[mt][0];
                acc[mt][nb][2] = biasReg[mt][1];
                acc[mt][nb][3] = biasReg[mt][1];
            }
        {
            const uint32_t* hrow = hp + buf * 2560 + sl * 640;
            #pragma unroll
            for (int ks = 0; ks < 6; ks++) {
                int t = ks >> 1, cp0 = (ks & 1) * 8;
                uint32_t b0[4], b1[4];
                #pragma unroll
                for (int nb = 0; nb < 4; nb++) {
                    int col = nb * 8 + gid + t;
                    b0[nb] = hrow[(cp0 + tid4) * 40 + col];
                    b1[nb] = hrow[(cp0 + tid4 + 4) * 40 + col];
                }
                #pragma unroll
                for (int mt = 0; mt < 2; mt++)
                    #pragma unroll
                    for (int nb = 0; nb < 4; nb++)
                        mma16(acc[mt][nb], aReg[mt][ks], b0[nb], b1[nb]);
            }
        }

        conv1_phase(&xs[(buf ^ 1) * 256 + sl * 64],
                    hp + (buf ^ 1) * 2560 + sl * 640, cp, sub, mh, m8,
                    wA0, wA1, wA2, bA, wB0, wB1, wB2, bB);

        {
            int b = tile * 4 + sl;
            if (b < B) {
                uint32_t* dst = h2p + (size_t)b * 512;
                #pragma unroll
                for (int mt = 0; mt < 2; mt++) {
                    int mtg = mh * 2 + mt;
                    #pragma unroll
                    for (int nb = 0; nb < 4; nb++) {
                        float plow  = fmaxf(fmaxf(acc[mt][nb][0], acc[mt][nb][1]), 0.0f);
                        float phigh = fmaxf(fmaxf(acc[mt][nb][2], acc[mt][nb][3]), 0.0f);
                        dst[(nb * 4 + tid4) * 32 + mtg * 8 + gid] = packbf(plow, phigh);
                    }
                }
            }
        }

        {
            int t2 = tile + 2 * CONV_GRID;
            int gi = t2 * 256 + tid;
            xR = (t2 < ntiles && gi < B * 64) ? x[gi] : 0.0f;
        }
        buf ^= 1;
    }
}

// ---------------------------------------------------------------------------
// Quantum helpers.
// ---------------------------------------------------------------------------
__device__ __forceinline__ void apply_ry(float st[16], float th, int mask)
{
    float s, c;
    sincosf(th * 0.5f, &s, &c);
    #pragma unroll
    for (int i = 0; i < 16; i++) {
        if (!(i & mask)) {
            int j = i | mask;
            float a = st[i], b = st[j];
            st[i] = c * a - s * b;
            st[j] = s * a + c * b;
        }
    }
}
__device__ __forceinline__ void apply_cnot(float st[16], int cm, int tm)
{
    #pragma unroll
    for (int i = 0; i < 16; i++) {
        if ((i & cm) && !(i & tm)) {
            int j = i | tm;
            float t = st[i]; st[i] = st[j]; st[j] = t;
        }
    }
}

// ---------------------------------------------------------------------------
// Kernel 2: fc GEMM, M=128/block, warp tile 32x32, cp.async 3-stage ring.
// Stage (u32): As [128][36] = 4608 | Bs [32 kp][72] = 2304  -> 6912.
// Hs [128][65] f32 overlaps stage region after mainloop.
// ---------------------------------------------------------------------------
#define FCS_STG 6912
#define FC_OFF_PW (3 * FCS_STG)
#define FC_OFF_FB (FC_OFF_PW + 256)
#define FC_OFF_PB (FC_OFF_FB + 64)
#define FC_OFF_QP (FC_OFF_PB + 4)
#define FC_OFF_PO (FC_OFF_QP + 24)
#define FC_OFF_QS (FC_OFF_PO + 8)
#define FC_SMEM_U32 (FC_OFF_QS + 512)

__global__ void __launch_bounds__(256, 2) k_fc(
    const uint32_t* __restrict__ h2p, const uint32_t* __restrict__ fcwp,
    const float* __restrict__ fcb, const float* __restrict__ prew,
    const float* __restrict__ preb, const float* __restrict__ qp,
    const float* __restrict__ postw, const float* __restrict__ postb,
    float* __restrict__ out, int B)
{
    extern __shared__ float sm[];
    uint32_t* smu  = (uint32_t*)sm;
    float* Hs      = sm;                 // overlaps stages after mainloop
    float* s_prew  = sm + FC_OFF_PW;
    float* s_fcb   = sm + FC_OFF_FB;
    float* s_preb  = sm + FC_OFF_PB;
    float* s_qp    = sm + FC_OFF_QP;
    float* s_po    = sm + FC_OFF_PO;
    float* qs      = sm + FC_OFF_QS;     // [128][4]

    int tid = threadIdx.x;
    int lane = tid & 31, warp = tid >> 5;
    int gid = lane >> 2, tid4 = lane & 3;
    int wm = warp & 3, wn = warp >> 2;
    int b0 = blockIdx.x * 128;

    s_prew[tid] = prew[tid];
    if (tid < 64) s_fcb[tid] = fcb[tid];
    if (tid < 4)  s_preb[tid] = preb[tid];
    if (tid < 24) s_qp[tid] = qp[tid];
    if (tid >= 24 && tid < 28) s_po[tid - 24] = postw[tid - 24];
    if (tid == 28) s_po[4] = postb[0];

    float acc[2][4][4];
    #pragma unroll
    for (int mt = 0; mt < 2; mt++)
        #pragma unroll
        for (int nb = 0; nb < 4; nb++)
            #pragma unroll
            for (int q = 0; q < 4; q++) acc[mt][nb][q] = 0.0f;

    uint32_t sbase = (uint32_t)__cvta_generic_to_shared(sm);

    // ---- cp.async lane maps ----
    // A: row = tid>>1 (2 threads/row), half = tid&1; 4 x 16B per thread.
    int a_row = tid >> 1, a_half = tid & 1;
    const uint32_t* a_g = h2p + (size_t)(b0 + a_row) * 512;
    uint32_t aD[4];
    #pragma unroll
    for (int i = 0; i < 4; i++)
        aD[i] = (uint32_t)(a_row * 36 + 4 * (a_half * 4 + i)) * 4;
    // B: kp = warp*4 + (lane&3); col halves lane>>2, +8.  2 x 16B per thread.
    int b_kp = warp * 4 + (lane & 3);
    int b_c  = lane >> 2;
    uint32_t bD0 = (uint32_t)(4608 + b_kp * 72 + 4 * b_c) * 4;
    uint32_t bD1 = (uint32_t)(4608 + b_kp * 72 + 4 * (b_c + 8)) * 4;
    const uint32_t* b_g = fcwp + b_kp * 64;

    #define FC_ISSUE(cc) do {                                              \
        uint32_t sb = sbase + (uint32_t)(((cc) % 3) * FCS_STG) * 4;        \
        cpasync16(sb + aD[0], a_g + (cc) * 32 + 4 * (a_half * 4 + 0));     \
        cpasync16(sb + aD[1], a_g + (cc) * 32 + 4 * (a_half * 4 + 1));     \
        cpasync16(sb + aD[2], a_g + (cc) * 32 + 4 * (a_half * 4 + 2));     \
        cpasync16(sb + aD[3], a_g + (cc) * 32 + 4 * (a_half * 4 + 3));     \
        cpasync16(sb + bD0, b_g + (cc) * 2048 + 4 * b_c);                  \
        cpasync16(sb + bD1, b_g + (cc) * 2048 + 4 * (b_c + 8));            \
    } while (0)

    FC_ISSUE(0); cp_commit();
    FC_ISSUE(1); cp_commit();

    for (int cc = 0; cc < 16; cc++) {
        cp_wait1();
        __syncthreads();
        if (cc + 2 < 16) FC_ISSUE(cc + 2);
        cp_commit();

        const uint32_t* ab = smu + (cc % 3) * FCS_STG;
        const uint32_t* bb = ab + 4608;
        #pragma unroll
        for (int ks = 0; ks < 4; ks++) {
            int kp0 = ks * 8;
            uint32_t a[2][4];
            #pragma unroll
            for (int mt = 0; mt < 2; mt++) {
                int r = wm * 32 + mt * 16 + gid;
                a[mt][0] = ab[r * 36 + kp0 + tid4];
                a[mt][1] = ab[(r + 8) * 36 + kp0 + tid4];
                a[mt][2] = ab[r * 36 + kp0 + tid4 + 4];
                a[mt][3] = ab[(r + 8) * 36 + kp0 + tid4 + 4];
            }
            #pragma unroll
            for (int nb = 0; nb < 4; nb++) {
                int col = wn * 32 + nb * 8 + gid;
                uint32_t bb0 = bb[(kp0 + tid4) * 72 + col];
                uint32_t bb1 = bb[(kp0 + tid4 + 4) * 72 + col];
                mma16(acc[0][nb], a[0], bb0, bb1);
                mma16(acc[1][nb], a[1], bb0, bb1);
            }
        }
    }
    cp_wait0();
    __syncthreads();     // all stage reads done; Hs may overwrite stages

    // ---- bias + relu -> Hs ----
    #pragma unroll
    for (int mt = 0; mt < 2; mt++) {
        int r = wm * 32 + mt * 16 + gid;
        #pragma unroll
        for (int nb = 0; nb < 4; nb++) {
            int cb = wn * 32 + nb * 8 + 2 * tid4;
            float bb0 = s_fcb[cb], bb1 = s_fcb[cb + 1];
            Hs[r * 65 + cb]           = fmaxf(acc[mt][nb][0] + bb0, 0.0f);
            Hs[r * 65 + cb + 1]       = fmaxf(acc[mt][nb][1] + bb1, 0.0f);
            Hs[(r + 8) * 65 + cb]     = fmaxf(acc[mt][nb][2] + bb0, 0.0f);
            Hs[(r + 8) * 65 + cb + 1] = fmaxf(acc[mt][nb][3] + bb1, 0.0f);
        }
    }
    __syncthreads();

    // ---- pre: 64 -> 4, tanh * pi/2 -> qs (512 tasks, 2 per thread) ----
    #pragma unroll
    for (int ii = 0; ii < 2; ii++) {
        int task = tid + 256 * ii;
        int s = task >> 2, wq = task & 3;
        const float* h = &Hs[s * 65];
        float d = s_preb[wq];
        #pragma unroll 8
        for (int j = 0; j < 64; j++) d = fmaf(h[j], s_prew[j * 4 + wq], d);
        qs[task] = tanhf(d) * 1.5707963267948966f;
    }
    __syncthreads();

    // ---- quantum circuit + post + sigmoid: threads 0..127 ----
    if (tid < 128 && b0 + tid < B) {
        float q0 = qs[tid * 4 + 0], q1 = qs[tid * 4 + 1];
        float q2 = qs[tid * 4 + 2], q3 = qs[tid * 4 + 3];

        float st[16];
        #pragma unroll
        for (int i = 0; i < 16; i++) st[i] = 0.25f;
        apply_ry(st, q0, 8);
        apply_ry(st, q1, 4);
        apply_ry(st, q2, 2);
        apply_ry(st, q3, 1);
        for (int k = 0; k < 6; k++) {
            apply_cnot(st, 8, 4);
            apply_cnot(st, 2, 1);
            apply_cnot(st, 4, 2);
            apply_ry(st, s_qp[4 * k + 0], 8);
            apply_ry(st, s_qp[4 * k + 1], 4);
            apply_ry(st, s_qp[4 * k + 2], 2);
            apply_ry(st, s_qp[4 * k + 3], 1);
        }

        float z0 = 0.f, z1 = 0.f, z2 = 0.f, z3 = 0.f;
        #pragma unroll
        for (int i = 0; i < 16; i++) {
            float pr = st[i] * st[i];
            z0 += (i & 8) ? -pr : pr;
            z1 += (i & 4) ? -pr : pr;
            z2 += (i & 2) ? -pr : pr;
            z3 += (i & 1) ? -pr : pr;
        }

        float t = s_po[4];
        t = fmaf(z0, s_po[0], t);
        t = fmaf(z1, s_po[1], t);
        t = fmaf(z2, s_po[2], t);
        t = fmaf(z3, s_po[3], t);
        out[b0 + tid] = 1.0f / (1.0f + expf(-t));
    }
}

// ---------------------------------------------------------------------------
extern "C" void kernel_launch(void* const* d_in, const int* in_sizes, int n_in,
                              void* d_out, int out_size)
{
    const float* x       = (const float*)d_in[0];
    const float* conv1_w = (const float*)d_in[1];
    const float* conv1_b = (const float*)d_in[2];
    const float* conv2_w = (const float*)d_in[3];
    const float* conv2_b = (const float*)d_in[4];
    const float* fc_w    = (const float*)d_in[5];
    const float* fc_b    = (const float*)d_in[6];
    const float* pre_w   = (const float*)d_in[7];
    const float* pre_b   = (const float*)d_in[8];
    const float* q_par   = (const float*)d_in[9];
    const float* post_w  = (const float*)d_in[10];
    const float* post_b  = (const float*)d_in[11];
    float* out = (float*)d_out;

    int B = in_sizes[0] / 64;
    if (B > BMAX) B = BMAX;
    int ntiles = (B + 3) / 4;

    uint32_t* h2p;
    uint32_t* fcwp;
    cudaGetSymbolAddress((void**)&h2p, g_h2p);
    cudaGetSymbolAddress((void**)&fcwp, g_fcwp);

    size_t conv_sm = CV_SMEM_U32 * 4;
    size_t fc_sm   = FC_SMEM_U32 * 4;
    cudaFuncSetAttribute(k_conv, cudaFuncAttributeMaxDynamicSharedMemorySize,
                         (int)conv_sm);
    cudaFuncSetAttribute(k_fc, cudaFuncAttributeMaxDynamicSharedMemorySize,
                         (int)fc_sm);

    k_conv<<<CONV_GRID, 256, conv_sm>>>(x, conv1_w, conv1_b, conv2_w, conv2_b,
                                        fc_w, h2p, fcwp, B, ntiles);
    k_fc<<<(B + 127) / 128, 256, fc_sm>>>(h2p, fcwp, fc_b, pre_w, pre_b, q_par,
                                          post_w, post_b, out, B);
}

// round 15
// speedup vs baseline: 1.2359x; 1.0003x over previous
#include <cuda_runtime.h>
#include <cuda_bf16.h>
#include <math.h>
#include <stdint.h>

// ---------------------------------------------------------------------------
// QuantumHybridCNN, bf16 MMA.
//  k_conv: persistent, double-buffered, pipelined conv1+conv2; conv1 stencil
//          in packed fma.rn.f32x2 (pool pair packed, weights pre-duplicated).
//  k_fc:   fc GEMM, 128 samples/block, warp tile m32xn32, cp.async 3-stage
//          ring, explicit fragment double-buffering inside each chunk.
//          + pre + tanh + 4-qubit circuit + post + sigmoid.
// h2p[b][q]: q = pos*32 + kp32, u32 = bf16x2(ch, ch+8), ch=(kp>>3)*16+(kp&7).
// g_fcwp[cc][kp][col] = bf16x2(fcw[ch*16+cc][col], fcw[(ch+8)*16+cc][col]).
// ---------------------------------------------------------------------------

#define BMAX 32768
__device__ uint32_t g_h2p[(size_t)BMAX * 512];
__device__ uint32_t g_fcwp[16 * 2048];

typedef unsigned long long u64;

__device__ __forceinline__ uint32_t packbf(float lo, float hi) {
    __nv_bfloat162 h = __floats2bfloat162_rn(lo, hi);
    return *(uint32_t*)&h;
}
__device__ __forceinline__ u64 pk2(float lo, float hi) {
    u64 r; asm("mov.b64 %0, {%1,%2};" : "=l"(r) : "f"(lo), "f"(hi)); return r;
}
__device__ __forceinline__ u64 fma2(u64 a, u64 b, u64 c) {
    u64 d; asm("fma.rn.f32x2 %0, %1, %2, %3;" : "=l"(d) : "l"(a), "l"(b), "l"(c));
    return d;
}
__device__ __forceinline__ float2 up2(u64 v) {
    float lo, hi; asm("mov.b64 {%0,%1}, %2;" : "=f"(lo), "=f"(hi) : "l"(v));
    return make_float2(lo, hi);
}

__device__ __forceinline__ void mma16(float d[4], const uint32_t a[4],
                                      uint32_t b0, uint32_t b1) {
    asm volatile(
        "mma.sync.aligned.m16n8k16.row.col.f32.bf16.bf16.f32 "
        "{%0,%1,%2,%3}, {%4,%5,%6,%7}, {%8,%9}, {%0,%1,%2,%3};"
        : "+f"(d[0]), "+f"(d[1]), "+f"(d[2]), "+f"(d[3])
        : "r"(a[0]), "r"(a[1]), "r"(a[2]), "r"(a[3]), "r"(b0), "r"(b1));
}

__device__ __forceinline__ void cpasync16(uint32_t smem_b, const void* g) {
    asm volatile("cp.async.ca.shared.global [%0], [%1], 16;"
                 :: "r"(smem_b), "l"(g));
}
__device__ __forceinline__ void cp_commit() {
    asm volatile("cp.async.commit_group;");
}
__device__ __forceinline__ void cp_wait1() {
    asm volatile("cp.async.wait_group 1;");
}
__device__ __forceinline__ void cp_wait0() {
    asm volatile("cp.async.wait_group 0;");
}

// conv1 + relu + pool, f32x2-packed over the pooled position pair.
// Thread owns channel pair (2cp, 2cp+1); STS staggered, conflict-free.
__device__ __forceinline__ void conv1_phase(
    const float* __restrict__ xr, uint32_t* __restrict__ hrow,
    int cp, int sub, int mh, int m8,
    u64 wA0p, u64 wA1p, u64 wA2p, u64 bAp,
    u64 wB0p, u64 wB1p, u64 wB2p, u64 bBp)
{
    #pragma unroll
    for (int i = 0; i < 8; i++) {
        int o = (m8 + i) & 7;
        int j = mh * 16 + sub * 8 + o;
        int pp = 2 * j;
        float xm  = (pp == 0)  ? 0.0f : xr[pp - 1];
        float x0  = xr[pp], x1 = xr[pp + 1];
        float xp2 = (pp == 62) ? 0.0f : xr[pp + 2];
        u64 xv0 = pk2(xm, x0);
        u64 xv1 = pk2(x0, x1);
        u64 xv2 = pk2(x1, xp2);
        u64 ya = fma2(wA0p, xv0, fma2(wA1p, xv1, fma2(wA2p, xv2, bAp)));
        u64 yb = fma2(wB0p, xv0, fma2(wB1p, xv1, fma2(wB2p, xv2, bBp)));
        float2 fa = up2(ya), fb = up2(yb);
        float vA = fmaxf(fmaxf(fa.x, fa.y), 0.0f);
        float vB = fmaxf(fmaxf(fb.x, fb.y), 0.0f);
        hrow[cp * 40 + j + 1] = packbf(vA, vB);
    }
}

// ---------------------------------------------------------------------------
// Kernel 1: conv1 + conv2, persistent + pipelined + fcw packing.
// ---------------------------------------------------------------------------
#define CV_XS 0
#define CV_HP 512
#define CV_WP (CV_HP + 5120)
#define CV_BS (CV_WP + 3456)
#define CV_SMEM_U32 (CV_BS + 64)
#define CONV_GRID 296

__global__ void __launch_bounds__(256, 2) k_conv(
    const float* __restrict__ x,
    const float* __restrict__ c1w, const float* __restrict__ c1b,
    const float* __restrict__ c2w, const float* __restrict__ c2b,
    const float* __restrict__ fcw,
    uint32_t* __restrict__ h2p, uint32_t* __restrict__ fcwp,
    int B, int ntiles)
{
    extern __shared__ float smf[];
    uint32_t* smu = (uint32_t*)smf;
    float*    xs  = smf + CV_XS;      // [2 buf][4 samples][64]
    uint32_t* hp  = smu + CV_HP;      // [2 buf][4 samples][16 cp][40]
    uint32_t* wpT = smu + CV_WP;      // [48 kp][72]
    float*    bs  = smf + CV_BS;      // [64]

    int tid = threadIdx.x;
    int lane = tid & 31, warp = tid >> 5;
    int gid = lane >> 2, tid4 = lane & 3;
    int sl = warp & 3;
    int mh = warp >> 2;

    // ---- one-time: pack fcw -> fcwp[cc][kp][col] (1 u32 / thread) ----
    {
        int i = blockIdx.x * 256 + tid;
        if (i < 32768) {
            int cc = i >> 11, kp = (i >> 6) & 31, col = i & 63;
            int ch = ((kp >> 3) << 4) + (kp & 7);
            fcwp[i] = packbf(fcw[(ch * 16 + cc) * 64 + col],
                             fcw[((ch + 8) * 16 + cc) * 64 + col]);
        }
    }

    // ---- one-time staging ----
    for (int i = tid; i < 3072; i += 256) {
        int kp = i >> 6, ch = i & 63;
        int k = 2 * kp, t = k >> 5, c = k & 31;
        wpT[kp * 72 + ch] = packbf(c2w[ch * 96 + c * 3 + t],
                                   c2w[ch * 96 + (c + 1) * 3 + t]);
    }
    if (tid < 64) bs[tid] = c2b[tid];
    if (tid < 128) {
        int bf = tid >> 6, s = (tid >> 4) & 3, cp = tid & 15;
        hp[bf * 2560 + s * 640 + cp * 40 + 0]  = 0u;
        hp[bf * 2560 + s * 640 + cp * 40 + 33] = 0u;
    }
    __syncthreads();

    // ---- persistent A fragments (weights) + bias registers ----
    uint32_t aReg[2][6][4];
    float biasReg[2][2];
    #pragma unroll
    for (int mt = 0; mt < 2; mt++) {
        int mtg = mh * 2 + mt;
        biasReg[mt][0] = bs[mtg * 16 + gid];
        biasReg[mt][1] = bs[mtg * 16 + gid + 8];
        #pragma unroll
        for (int ks = 0; ks < 6; ks++) {
            int kp0 = ks * 8;
            aReg[mt][ks][0] = wpT[(kp0 + tid4) * 72 + mtg * 16 + gid];
            aReg[mt][ks][1] = wpT[(kp0 + tid4) * 72 + mtg * 16 + gid + 8];
            aReg[mt][ks][2] = wpT[(kp0 + tid4 + 4) * 72 + mtg * 16 + gid];
            aReg[mt][ks][3] = wpT[(kp0 + tid4 + 4) * 72 + mtg * 16 + gid + 8];
        }
    }

    // conv1 weights, duplicate-packed for f32x2 (loop-invariant)
    int cp = lane >> 1, sub = lane & 1;
    int m8 = (cp >> 2) + 4 * sub;
    u64 wA0p, wA1p, wA2p, bAp, wB0p, wB1p, wB2p, bBp;
    {
        float wA0 = __ldg(&c1w[(2 * cp) * 3 + 0]);
        float wA1 = __ldg(&c1w[(2 * cp) * 3 + 1]);
        float wA2 = __ldg(&c1w[(2 * cp) * 3 + 2]);
        float bA  = __ldg(&c1b[2 * cp]);
        float wB0 = __ldg(&c1w[(2 * cp + 1) * 3 + 0]);
        float wB1 = __ldg(&c1w[(2 * cp + 1) * 3 + 1]);
        float wB2 = __ldg(&c1w[(2 * cp + 1) * 3 + 2]);
        float bB  = __ldg(&c1b[2 * cp + 1]);
        wA0p = pk2(wA0, wA0); wA1p = pk2(wA1, wA1); wA2p = pk2(wA2, wA2);
        bAp  = pk2(bA, bA);
        wB0p = pk2(wB0, wB0); wB1p = pk2(wB1, wB1); wB2p = pk2(wB2, wB2);
        bBp  = pk2(bB, bB);
    }

    // ---- prologue ----
    int tile0 = blockIdx.x;
    float xR;
    {
        int gi = tile0 * 256 + tid;
        xR = (tile0 < ntiles && gi < B * 64) ? x[gi] : 0.0f;
        xs[tid] = xR;
    }
    __syncthreads();
    conv1_phase(&xs[sl * 64], hp + sl * 640, cp, sub, mh, m8,
                wA0p, wA1p, wA2p, bAp, wB0p, wB1p, wB2p, bBp);
    {
        int t1 = tile0 + CONV_GRID;
        int gi = t1 * 256 + tid;
        xR = (t1 < ntiles && gi < B * 64) ? x[gi] : 0.0f;
    }

    int buf = 0;
    for (int tile = tile0; tile < ntiles; tile += CONV_GRID) {
        xs[(buf ^ 1) * 256 + tid] = xR;
        __syncthreads();

        float acc[2][4][4];
        #pragma unroll
        for (int mt = 0; mt < 2; mt++)
            #pragma unroll
            for (int nb = 0; nb < 4; nb++) {
                acc[mt][nb][0] = biasReg[mt][0];
                acc[mt][nb][1] = biasReg[mt][0];
                acc[mt][nb][2] = biasReg[mt][1];
                acc[mt][nb][3] = biasReg[mt][1];
            }
        {
            const uint32_t* hrow = hp + buf * 2560 + sl * 640;
            #pragma unroll
            for (int ks = 0; ks < 6; ks++) {
                int t = ks >> 1, cp0 = (ks & 1) * 8;
                uint32_t b0[4], b1[4];
                #pragma unroll
                for (int nb = 0; nb < 4; nb++) {
                    int col = nb * 8 + gid + t;
                    b0[nb] = hrow[(cp0 + tid4) * 40 + col];
                    b1[nb] = hrow[(cp0 + tid4 + 4) * 40 + col];
                }
                #pragma unroll
                for (int mt = 0; mt < 2; mt++)
                    #pragma unroll
                    for (int nb = 0; nb < 4; nb++)
                        mma16(acc[mt][nb], aReg[mt][ks], b0[nb], b1[nb]);
            }
        }

        conv1_phase(&xs[(buf ^ 1) * 256 + sl * 64],
                    hp + (buf ^ 1) * 2560 + sl * 640, cp, sub, mh, m8,
                    wA0p, wA1p, wA2p, bAp, wB0p, wB1p, wB2p, bBp);

        {
            int b = tile * 4 + sl;
            if (b < B) {
                uint32_t* dst = h2p + (size_t)b * 512;
                #pragma unroll
                for (int mt = 0; mt < 2; mt++) {
                    int mtg = mh * 2 + mt;
                    #pragma unroll
                    for (int nb = 0; nb < 4; nb++) {
                        float plow  = fmaxf(fmaxf(acc[mt][nb][0], acc[mt][nb][1]), 0.0f);
                        float phigh = fmaxf(fmaxf(acc[mt][nb][2], acc[mt][nb][3]), 0.0f);
                        dst[(nb * 4 + tid4) * 32 + mtg * 8 + gid] = packbf(plow, phigh);
                    }
                }
            }
        }

        {
            int t2 = tile + 2 * CONV_GRID;
            int gi = t2 * 256 + tid;
            xR = (t2 < ntiles && gi < B * 64) ? x[gi] : 0.0f;
        }
        buf ^= 1;
    }
}

// ---------------------------------------------------------------------------
// Quantum helpers.
// ---------------------------------------------------------------------------
__device__ __forceinline__ void apply_ry(float st[16], float th, int mask)
{
    float s, c;
    sincosf(th * 0.5f, &s, &c);
    #pragma unroll
    for (int i = 0; i < 16; i++) {
        if (!(i & mask)) {
            int j = i | mask;
            float a = st[i], b = st[j];
            st[i] = c * a - s * b;
            st[j] = s * a + c * b;
        }
    }
}
__device__ __forceinline__ void apply_cnot(float st[16], int cm, int tm)
{
    #pragma unroll
    for (int i = 0; i < 16; i++) {
        if ((i & cm) && !(i & tm)) {
            int j = i | tm;
            float t = st[i]; st[i] = st[j]; st[j] = t;
        }
    }
}

// fc fragment loader (m32 x n32 warp tile, one k16 step)
__device__ __forceinline__ void fc_load_frags(
    const uint32_t* __restrict__ ab, const uint32_t* __restrict__ bb,
    int ks, int wm, int wn, int gid, int tid4,
    uint32_t afr[2][4], uint32_t bfr[4][2])
{
    int kp0 = ks * 8;
    #pragma unroll
    for (int mt = 0; mt < 2; mt++) {
        int r = wm * 32 + mt * 16 + gid;
        afr[mt][0] = ab[r * 36 + kp0 + tid4];
        afr[mt][1] = ab[(r + 8) * 36 + kp0 + tid4];
        afr[mt][2] = ab[r * 36 + kp0 + tid4 + 4];
        afr[mt][3] = ab[(r + 8) * 36 + kp0 + tid4 + 4];
    }
    #pragma unroll
    for (int nb = 0; nb < 4; nb++) {
        int col = wn * 32 + nb * 8 + gid;
        bfr[nb][0] = bb[(kp0 + tid4) * 72 + col];
        bfr[nb][1] = bb[(kp0 + tid4 + 4) * 72 + col];
    }
}

// ---------------------------------------------------------------------------
// Kernel 2: fc GEMM, M=128/block, warp tile 32x32, cp.async 3-stage ring,
// fragment double-buffering. Hs overlaps stage smem after mainloop.
// Stage (u32): As [128][36] = 4608 | Bs [32 kp][72] = 2304  -> 6912.
// ---------------------------------------------------------------------------
#define FCS_STG 6912
#define FC_OFF_PW (3 * FCS_STG)
#define FC_OFF_FB (FC_OFF_PW + 256)
#define FC_OFF_PB (FC_OFF_FB + 64)
#define FC_OFF_QP (FC_OFF_PB + 4)
#define FC_OFF_PO (FC_OFF_QP + 24)
#define FC_OFF_QS (FC_OFF_PO + 8)
#define FC_SMEM_U32 (FC_OFF_QS + 512)

__global__ void __launch_bounds__(256, 2) k_fc(
    const uint32_t* __restrict__ h2p, const uint32_t* __restrict__ fcwp,
    const float* __restrict__ fcb, const float* __restrict__ prew,
    const float* __restrict__ preb, const float* __restrict__ qp,
    const float* __restrict__ postw, const float* __restrict__ postb,
    float* __restrict__ out, int B)
{
    extern __shared__ float sm[];
    uint32_t* smu  = (uint32_t*)sm;
    float* Hs      = sm;                 // overlaps stages after mainloop
    float* s_prew  = sm + FC_OFF_PW;
    float* s_fcb   = sm + FC_OFF_FB;
    float* s_preb  = sm + FC_OFF_PB;
    float* s_qp    = sm + FC_OFF_QP;
    float* s_po    = sm + FC_OFF_PO;
    float* qs      = sm + FC_OFF_QS;     // [128][4]

    int tid = threadIdx.x;
    int lane = tid & 31, warp = tid >> 5;
    int gid = lane >> 2, tid4 = lane & 3;
    int wm = warp & 3, wn = warp >> 2;
    int b0 = blockIdx.x * 128;

    s_prew[tid] = prew[tid];
    if (tid < 64) s_fcb[tid] = fcb[tid];
    if (tid < 4)  s_preb[tid] = preb[tid];
    if (tid < 24) s_qp[tid] = qp[tid];
    if (tid >= 24 && tid < 28) s_po[tid - 24] = postw[tid - 24];
    if (tid == 28) s_po[4] = postb[0];

    float acc[2][4][4];
    #pragma unroll
    for (int mt = 0; mt < 2; mt++)
        #pragma unroll
        for (int nb = 0; nb < 4; nb++)
            #pragma unroll
            for (int q = 0; q < 4; q++) acc[mt][nb][q] = 0.0f;

    uint32_t sbase = (uint32_t)__cvta_generic_to_shared(sm);

    // ---- cp.async lane maps ----
    int a_row = tid >> 1, a_half = tid & 1;
    const uint32_t* a_g = h2p + (size_t)(b0 + a_row) * 512;
    uint32_t aD[4];
    #pragma unroll
    for (int i = 0; i < 4; i++)
        aD[i] = (uint32_t)(a_row * 36 + 4 * (a_half * 4 + i)) * 4;
    int b_kp = warp * 4 + (lane & 3);
    int b_c  = lane >> 2;
    uint32_t bD0 = (uint32_t)(4608 + b_kp * 72 + 4 * b_c) * 4;
    uint32_t bD1 = (uint32_t)(4608 + b_kp * 72 + 4 * (b_c + 8)) * 4;
    const uint32_t* b_g = fcwp + b_kp * 64;

    #define FC_ISSUE(cc) do {                                              \
        uint32_t sb = sbase + (uint32_t)(((cc) % 3) * FCS_STG) * 4;        \
        cpasync16(sb + aD[0], a_g + (cc) * 32 + 4 * (a_half * 4 + 0));     \
        cpasync16(sb + aD[1], a_g + (cc) * 32 + 4 * (a_half * 4 + 1));     \
        cpasync16(sb + aD[2], a_g + (cc) * 32 + 4 * (a_half * 4 + 2));     \
        cpasync16(sb + aD[3], a_g + (cc) * 32 + 4 * (a_half * 4 + 3));     \
        cpasync16(sb + bD0, b_g + (cc) * 2048 + 4 * b_c);                  \
        cpasync16(sb + bD1, b_g + (cc) * 2048 + 4 * (b_c + 8));            \
    } while (0)

    FC_ISSUE(0); cp_commit();
    FC_ISSUE(1); cp_commit();

    for (int cc = 0; cc < 16; cc++) {
        cp_wait1();
        __syncthreads();
        if (cc + 2 < 16) FC_ISSUE(cc + 2);
        cp_commit();

        const uint32_t* ab = smu + (cc % 3) * FCS_STG;
        const uint32_t* bb = ab + 4608;

        uint32_t afr[2][2][4], bfr[2][4][2];
        fc_load_frags(ab, bb, 0, wm, wn, gid, tid4, afr[0], bfr[0]);
        #pragma unroll
        for (int ks = 0; ks < 4; ks++) {
            int cur = ks & 1;
            if (ks < 3)
                fc_load_frags(ab, bb, ks + 1, wm, wn, gid, tid4,
                              afr[cur ^ 1], bfr[cur ^ 1]);
            #pragma unroll
            for (int nb = 0; nb < 4; nb++) {
                mma16(acc[0][nb], afr[cur][0], bfr[cur][nb][0], bfr[cur][nb][1]);
                mma16(acc[1][nb], afr[cur][1], bfr[cur][nb][0], bfr[cur][nb][1]);
            }
        }
    }
    cp_wait0();
    __syncthreads();     // all stage reads done; Hs may overwrite stages

    // ---- bias + relu -> Hs ----
    #pragma unroll
    for (int mt = 0; mt < 2; mt++) {
        int r = wm * 32 + mt * 16 + gid;
        #pragma unroll
        for (int nb = 0; nb < 4; nb++) {
            int cb = wn * 32 + nb * 8 + 2 * tid4;
            float bb0 = s_fcb[cb], bb1 = s_fcb[cb + 1];
            Hs[r * 65 + cb]           = fmaxf(acc[mt][nb][0] + bb0, 0.0f);
            Hs[r * 65 + cb + 1]       = fmaxf(acc[mt][nb][1] + bb1, 0.0f);
            Hs[(r + 8) * 65 + cb]     = fmaxf(acc[mt][nb][2] + bb0, 0.0f);
            Hs[(r + 8) * 65 + cb + 1] = fmaxf(acc[mt][nb][3] + bb1, 0.0f);
        }
    }
    __syncthreads();

    // ---- pre: 64 -> 4, tanh * pi/2 -> qs (512 tasks, 2 per thread) ----
    #pragma unroll
    for (int ii = 0; ii < 2; ii++) {
        int task = tid + 256 * ii;
        int s = task >> 2, wq = task & 3;
        const float* h = &Hs[s * 65];
        float d = s_preb[wq];
        #pragma unroll 8
        for (int j = 0; j < 64; j++) d = fmaf(h[j], s_prew[j * 4 + wq], d);
        qs[task] = tanhf(d) * 1.5707963267948966f;
    }
    __syncthreads();

    // ---- quantum circuit + post + sigmoid: threads 0..127 ----
    if (tid < 128 && b0 + tid < B) {
        float q0 = qs[tid * 4 + 0], q1 = qs[tid * 4 + 1];
        float q2 = qs[tid * 4 + 2], q3 = qs[tid * 4 + 3];

        float st[16];
        #pragma unroll
        for (int i = 0; i < 16; i++) st[i] = 0.25f;
        apply_ry(st, q0, 8);
        apply_ry(st, q1, 4);
        apply_ry(st, q2, 2);
        apply_ry(st, q3, 1);
        for (int k = 0; k < 6; k++) {
            apply_cnot(st, 8, 4);
            apply_cnot(st, 2, 1);
            apply_cnot(st, 4, 2);
            apply_ry(st, s_qp[4 * k + 0], 8);
            apply_ry(st, s_qp[4 * k + 1], 4);
            apply_ry(st, s_qp[4 * k + 2], 2);
            apply_ry(st, s_qp[4 * k + 3], 1);
        }

        float z0 = 0.f, z1 = 0.f, z2 = 0.f, z3 = 0.f;
        #pragma unroll
        for (int i = 0; i < 16; i++) {
            float pr = st[i] * st[i];
            z0 += (i & 8) ? -pr : pr;
            z1 += (i & 4) ? -pr : pr;
            z2 += (i & 2) ? -pr : pr;
            z3 += (i & 1) ? -pr : pr;
        }

        float t = s_po[4];
        t = fmaf(z0, s_po[0], t);
        t = fmaf(z1, s_po[1], t);
        t = fmaf(z2, s_po[2], t);
        t = fmaf(z3, s_po[3], t);
        out[b0 + tid] = 1.0f / (1.0f + expf(-t));
    }
}

// ---------------------------------------------------------------------------
extern "C" void kernel_launch(void* const* d_in, const int* in_sizes, int n_in,
                              void* d_out, int out_size)
{
    const float* x       = (const float*)d_in[0];
    const float* conv1_w = (const float*)d_in[1];
    const float* conv1_b = (const float*)d_in[2];
    const float* conv2_w = (const float*)d_in[3];
    const float* conv2_b = (const float*)d_in[4];
    const float* fc_w    = (const float*)d_in[5];
    const float* fc_b    = (const float*)d_in[6];
    const float* pre_w   = (const float*)d_in[7];
    const float* pre_b   = (const float*)d_in[8];
    const float* q_par   = (const float*)d_in[9];
    const float* post_w  = (const float*)d_in[10];
    const float* post_b  = (const float*)d_in[11];
    float* out = (float*)d_out;

    int B = in_sizes[0] / 64;
    if (B > BMAX) B = BMAX;
    int ntiles = (B + 3) / 4;

    uint32_t* h2p;
    uint32_t* fcwp;
    cudaGetSymbolAddress((void**)&h2p, g_h2p);
    cudaGetSymbolAddress((void**)&fcwp, g_fcwp);

    size_t conv_sm = CV_SMEM_U32 * 4;
    size_t fc_sm   = FC_SMEM_U32 * 4;
    cudaFuncSetAttribute(k_conv, cudaFuncAttributeMaxDynamicSharedMemorySize,
                         (int)conv_sm);
    cudaFuncSetAttribute(k_fc, cudaFuncAttributeMaxDynamicSharedMemorySize,
                         (int)fc_sm);

    k_conv<<<CONV_GRID, 256, conv_sm>>>(x, conv1_w, conv1_b, conv2_w, conv2_b,
                                        fc_w, h2p, fcwp, B, ntiles);
    k_fc<<<(B + 127) / 128, 256, fc_sm>>>(h2p, fcwp, fc_b, pre_w, pre_b, q_par,
                                          post_w, post_b, out, B);
}